// round 1
// baseline (speedup 1.0000x reference)
#include <cuda_runtime.h>
#include <cuda_bf16.h>
#include <cstdint>

// Problem constants
#define V_  262144
#define E_  524288
#define NG  8192
#define H_  128

// ---------------- scratch (device globals; zero-initialized at module load) ----
__device__ float    g_x[(size_t)V_ * H_];     // current node features
__device__ float    g_e[(size_t)E_ * H_];     // edge embeddings
__device__ float    g_agg[(size_t)V_ * H_];   // message aggregation (kept zero between calls)
__device__ float    g_h[(size_t)V_ * H_];     // layer temp
__device__ float    g_logit[V_];
__device__ unsigned g_menc[NG];
__device__ float    g_den[NG];

// ---------------- helpers ------------------------------------------------------
__device__ __forceinline__ unsigned encf(float f) {
    unsigned u = __float_as_uint(f);
    return (u & 0x80000000u) ? ~u : (u | 0x80000000u);
}
__device__ __forceinline__ float decf(unsigned u) {
    return (u & 0x80000000u) ? __uint_as_float(u & 0x7fffffffu) : __uint_as_float(~u);
}
__device__ __forceinline__ void atomic_add4(float4* p, float4 v) {
#if __CUDA_ARCH__ >= 900
    atomicAdd(p, v);
#else
    float* f = (float*)p;
    atomicAdd(f + 0, v.x); atomicAdd(f + 1, v.y);
    atomicAdd(f + 2, v.z); atomicAdd(f + 3, v.w);
#endif
}

// ---------------- edge embedding: e = relu(attr @ W_edge + b) ------------------
// one block = 128 edges, 128 threads (thread = output column)
__global__ __launch_bounds__(128) void edge_embed_k(
    const float* __restrict__ attr, const float* __restrict__ Wedge,
    const float* __restrict__ bedge)
{
    __shared__ float Ws[16 * 128];
    __shared__ float Ae[128 * 16];
    __shared__ float bs[128];
    const int tid = threadIdx.x;
    const int e0 = blockIdx.x * 128;
    #pragma unroll
    for (int i = tid; i < 16 * 128; i += 128) Ws[i] = Wedge[i];
    bs[tid] = bedge[tid];
    #pragma unroll
    for (int i = tid; i < 128 * 16; i += 128) Ae[i] = attr[(size_t)e0 * 16 + i];
    __syncthreads();
    for (int ee = 0; ee < 128; ee++) {
        float s = bs[tid];
        #pragma unroll
        for (int k = 0; k < 16; k++) s = fmaf(Ae[ee * 16 + k], Ws[k * 128 + tid], s);
        g_e[(size_t)(e0 + ee) * 128 + tid] = fmaxf(s, 0.f);
    }
}

// ---------------- scatter: agg[dst] += relu(x[src] + e) -----------------------
// one warp = one edge; lane handles 4 floats (float4), vector atomic
__global__ __launch_bounds__(256) void scatter_k(
    const int* __restrict__ src, const int* __restrict__ dst)
{
    const int warp = (blockIdx.x * blockDim.x + threadIdx.x) >> 5;
    const int lane = threadIdx.x & 31;
    if (warp >= E_) return;
    const int s = src[warp];
    const int d = dst[warp];
    float4 xv = *(const float4*)(g_x + (size_t)s * 128 + lane * 4);
    float4 ev = *(const float4*)(g_e + (size_t)warp * 128 + lane * 4);
    float4 m;
    m.x = fmaxf(xv.x + ev.x, 0.f);
    m.y = fmaxf(xv.y + ev.y, 0.f);
    m.z = fmaxf(xv.z + ev.z, 0.f);
    m.w = fmaxf(xv.w + ev.w, 0.f);
    atomic_add4((float4*)(g_agg + (size_t)d * 128 + lane * 4), m);
}

// ---------------- fused tiled GEMM ---------------------------------------------
// 128x128 output tile per block, 256 threads, 8x8 micro-tile, BK=16.
// MODE 0 (EMB):  A = [x_upd | Zc[g] | Zb[g]] (K=384), out = relu -> g_x
// MODE 1 (L1):   A = g_x + g_agg (K=128, zeroes g_agg), out = relu -> g_h
// MODE 2 (L2):   A = g_h (K=128), g_x += relu(acc+b)
// MODE 3 (HEAD): A = [g_x | x_inp] (K=192), relu, dot W_mlp2 -> g_logit
template <int K, int MODE>
__global__ __launch_bounds__(256) void gemm_k(
    const float* __restrict__ A0, const float* __restrict__ A1,
    const float* __restrict__ A2, const int* __restrict__ n2g,
    const float* __restrict__ W,  const float* __restrict__ bias,
    const float* __restrict__ w2, const float* __restrict__ b2s)
{
    __shared__ float As[128][16];
    __shared__ float Bs[16][128];
    const int tid = threadIdx.x;
    const int tx = tid & 15, ty = tid >> 4;
    const int rowBase = blockIdx.x * 128;

    float acc[8][8];
    #pragma unroll
    for (int i = 0; i < 8; i++)
        #pragma unroll
        for (int j = 0; j < 8; j++) acc[i][j] = 0.f;

    for (int k0 = 0; k0 < K; k0 += 16) {
        // load A tile (128x16), 2 float4 per thread
        #pragma unroll
        for (int it = 0; it < 2; it++) {
            int t = tid + it * 256;
            int m = t >> 2;
            int kq = (t & 3) << 2;
            int r = rowBase + m;
            int k = k0 + kq;
            float4 v;
            if (MODE == 0) {
                if (k < 128) {
                    v = *(const float4*)(A0 + (size_t)r * 128 + k);
                } else {
                    int gg = n2g[r];
                    if (k < 256) v = *(const float4*)(A1 + (size_t)gg * 128 + (k - 128));
                    else         v = *(const float4*)(A2 + (size_t)gg * 128 + (k - 256));
                }
            } else if (MODE == 1) {
                size_t off = (size_t)r * 128 + k;
                float4 a = *(const float4*)(g_x + off);
                float4 b = *(const float4*)(g_agg + off);
                v = make_float4(a.x + b.x, a.y + b.y, a.z + b.z, a.w + b.w);
                *(float4*)(g_agg + off) = make_float4(0.f, 0.f, 0.f, 0.f);
            } else if (MODE == 2) {
                v = *(const float4*)(g_h + (size_t)r * 128 + k);
            } else {
                if (k < 128) v = *(const float4*)(g_x + (size_t)r * 128 + k);
                else         v = *(const float4*)(A0 + (size_t)r * 64 + (k - 128));
            }
            *(float4*)&As[m][kq] = v;
        }
        // load B tile (16x128)
        #pragma unroll
        for (int it = 0; it < 2; it++) {
            int t = tid + it * 256;
            int kk = t >> 5;
            int n = (t & 31) << 2;
            *(float4*)&Bs[kk][n] = *(const float4*)(W + (size_t)(k0 + kk) * 128 + n);
        }
        __syncthreads();
        #pragma unroll
        for (int kk = 0; kk < 16; kk++) {
            float a[8], b[8];
            *(float4*)&b[0] = *(float4*)&Bs[kk][tx * 8];
            *(float4*)&b[4] = *(float4*)&Bs[kk][tx * 8 + 4];
            #pragma unroll
            for (int i = 0; i < 8; i++) a[i] = As[ty * 8 + i][kk];
            #pragma unroll
            for (int i = 0; i < 8; i++)
                #pragma unroll
                for (int j = 0; j < 8; j++) acc[i][j] = fmaf(a[i], b[j], acc[i][j]);
        }
        __syncthreads();
    }

    // bias fragment
    float bv[8];
    *(float4*)&bv[0] = *(const float4*)(bias + tx * 8);
    *(float4*)&bv[4] = *(const float4*)(bias + tx * 8 + 4);

    if (MODE == 3) {
        float wv[8];
        *(float4*)&wv[0] = *(const float4*)(w2 + tx * 8);
        *(float4*)&wv[4] = *(const float4*)(w2 + tx * 8 + 4);
        float bb = b2s[0];
        #pragma unroll
        for (int i = 0; i < 8; i++) {
            float p = 0.f;
            #pragma unroll
            for (int j = 0; j < 8; j++) {
                float t = fmaxf(acc[i][j] + bv[j], 0.f);
                p = fmaf(t, wv[j], p);
            }
            #pragma unroll
            for (int off = 8; off; off >>= 1)
                p += __shfl_down_sync(0xffffffffu, p, off, 16);
            if (tx == 0) g_logit[rowBase + ty * 8 + i] = p + bb;
        }
    } else {
        #pragma unroll
        for (int i = 0; i < 8; i++) {
            size_t off = (size_t)(rowBase + ty * 8 + i) * 128 + tx * 8;
            float o[8];
            #pragma unroll
            for (int j = 0; j < 8; j++) o[j] = fmaxf(acc[i][j] + bv[j], 0.f);
            if (MODE == 2) {
                float4 x0 = *(float4*)(g_x + off);
                float4 x1 = *(float4*)(g_x + off + 4);
                x0.x += o[0]; x0.y += o[1]; x0.z += o[2]; x0.w += o[3];
                x1.x += o[4]; x1.y += o[5]; x1.z += o[6]; x1.w += o[7];
                *(float4*)(g_x + off) = x0;
                *(float4*)(g_x + off + 4) = x1;
            } else {
                float* dst = (MODE == 0) ? g_x : g_h;
                *(float4*)(dst + off)     = make_float4(o[0], o[1], o[2], o[3]);
                *(float4*)(dst + off + 4) = make_float4(o[4], o[5], o[6], o[7]);
            }
        }
    }
}

// ---------------- segment softmax ----------------------------------------------
__global__ void zero_small_k() {
    int i = blockIdx.x * blockDim.x + threadIdx.x;
    if (i < NG) { g_menc[i] = 0u; g_den[i] = 0.f; }
}
__global__ void seg_max_k(const int* __restrict__ n2g) {
    int i = blockIdx.x * blockDim.x + threadIdx.x;
    if (i >= V_) return;
    atomicMax(&g_menc[n2g[i]], encf(g_logit[i]));
}
__global__ void seg_exp_k(const int* __restrict__ n2g, float* __restrict__ out) {
    int i = blockIdx.x * blockDim.x + threadIdx.x;
    if (i >= V_) return;
    int gg = n2g[i];
    float m = decf(g_menc[gg]);
    float ex = expf(g_logit[i] - m);
    out[i] = ex;
    atomicAdd(&g_den[gg], ex);
}
__global__ void seg_div_k(const int* __restrict__ n2g, float* __restrict__ out) {
    int i = blockIdx.x * blockDim.x + threadIdx.x;
    if (i >= V_) return;
    out[i] = out[i] / g_den[n2g[i]];
}

// ---------------- launch --------------------------------------------------------
extern "C" void kernel_launch(void* const* d_in, const int* in_sizes, int n_in,
                              void* d_out, int out_size)
{
    const float* x_inp   = (const float*)d_in[0];
    const int*   eidx    = (const int*)  d_in[1];   // (2,E): [src | dst]
    const float* eattr   = (const float*)d_in[2];
    const float* x_upd   = (const float*)d_in[3];
    const float* Zc      = (const float*)d_in[4];
    const float* Zb      = (const float*)d_in[5];
    const int*   n2g     = (const int*)  d_in[6];
    const float* W_emb   = (const float*)d_in[7];
    const float* b_emb   = (const float*)d_in[8];
    const float* W_edge  = (const float*)d_in[9];
    const float* b_edge  = (const float*)d_in[10];
    const float* W1      = (const float*)d_in[11];
    const float* b1      = (const float*)d_in[12];
    const float* W2      = (const float*)d_in[13];
    const float* b2      = (const float*)d_in[14];
    const float* W_mlp1  = (const float*)d_in[15];
    const float* b_mlp1  = (const float*)d_in[16];
    const float* W_mlp2  = (const float*)d_in[17];
    const float* b_mlp2  = (const float*)d_in[18];
    float* out = (float*)d_out;

    const int GEMM_BLOCKS = V_ / 128;   // 2048

    zero_small_k<<<(NG + 255) / 256, 256>>>();
    edge_embed_k<<<E_ / 128, 128>>>(eattr, W_edge, b_edge);
    gemm_k<384, 0><<<GEMM_BLOCKS, 256>>>(x_upd, Zc, Zb, n2g, W_emb, b_emb, nullptr, nullptr);

    for (int l = 0; l < 4; l++) {
        scatter_k<<<E_ / 8, 256>>>(eidx, eidx + E_);
        gemm_k<128, 1><<<GEMM_BLOCKS, 256>>>(nullptr, nullptr, nullptr, nullptr,
                                             W1 + (size_t)l * 128 * 128, b1 + (size_t)l * 128,
                                             nullptr, nullptr);
        gemm_k<128, 2><<<GEMM_BLOCKS, 256>>>(nullptr, nullptr, nullptr, nullptr,
                                             W2 + (size_t)l * 128 * 128, b2 + (size_t)l * 128,
                                             nullptr, nullptr);
    }

    gemm_k<192, 3><<<GEMM_BLOCKS, 256>>>(x_inp, nullptr, nullptr, nullptr,
                                         W_mlp1, b_mlp1, W_mlp2, b_mlp2);

    seg_max_k<<<V_ / 256, 256>>>(n2g);
    seg_exp_k<<<V_ / 256, 256>>>(n2g, out);
    seg_div_k<<<V_ / 256, 256>>>(n2g, out);
}